// round 2
// baseline (speedup 1.0000x reference)
#include <cuda_runtime.h>
#include <math.h>

#define Bq 4
#define Nv 12000
#define FN 24000
#define C 128
#define NNZ (48 * FN)
#define EPSV 1e-5f

#define RV (Bq * Nv)   // 48000 vertex rows
#define RF (Bq * FN)   // 96000 face rows

// ---------------- scratch (device globals: allocation-free) ----------------
__device__ float  g_v[RV * C];          // vertex features
__device__ float  g_f[RF * C];          // face features
__device__ float  g_msg[RF * C];        // message buffer / temp x in avg blocks
__device__ float  g_xcat[RF * 2 * C];   // concat+elu GEMM input
__device__ double g_sum[256];           // per-channel sum (double!)
__device__ double g_sumsq[256];         // per-channel sumsq (double!)
__device__ float  g_scale[256];         // BN scale  a_k = gamma*rsqrt(var+eps)
__device__ float  g_shift[256];         // BN shift  beta - mean*a
__device__ double g_avgsum[Bq * C];
__device__ double g_masksum[Bq];

__device__ __forceinline__ float elu_f(float x) {
    return x > 0.f ? x : expm1f(x);
}

// ---------------- conv1: v = inputs @ W1 + b1 ----------------
__global__ void conv1_kernel(const float* __restrict__ in,
                             const float* __restrict__ W1,
                             const float* __restrict__ b1) {
    int idx = blockIdx.x * blockDim.x + threadIdx.x;
    if (idx >= RV * C) return;
    int r = idx >> 7, c = idx & 127;
    float x0 = in[r * 3 + 0], x1 = in[r * 3 + 1], x2 = in[r * 3 + 2];
    g_v[idx] = x0 * W1[c] + x1 * W1[128 + c] + x2 * W1[256 + c] + b1[c];
}

// ---------------- sparse COO scatter: out[b,r,0:32] += val * in[b,c,0:32] ----------------
__global__ void scatter_kernel(const int* __restrict__ rows,
                               const int* __restrict__ cols,
                               const float* __restrict__ vals,
                               const float* __restrict__ in,
                               float* __restrict__ out,
                               int inStride, int outStride) {
    int t = threadIdx.x;                      // 256 threads: 2 edges
    int e = blockIdx.x * 2 + (t >> 7);
    int lt = t & 127;
    int b = lt >> 5, k = lt & 31;
    int r = rows[e], c = cols[e];
    float val = vals[e];
    atomicAdd(&out[b * outStride + r * 32 + k],
              val * __ldg(&in[b * inStride + c * 32 + k]));
}

// ---------------- xcat = elu(concat([a, m], -1)) + fused double-precision stats ----------------
#define EC_ROWS 64
__global__ void elucat_stats_kernel(const float* __restrict__ a,
                                    const float* __restrict__ m,
                                    float* __restrict__ xc) {
    int c = threadIdx.x;                      // 128
    int r0 = blockIdx.x * EC_ROWS;
    float s1 = 0.f, q1 = 0.f, s2 = 0.f, q2 = 0.f;
    for (int i = 0; i < EC_ROWS; i++) {
        int row = r0 + i;
        float xa = elu_f(a[row * 128 + c]);
        float xm = elu_f(m[row * 128 + c]);
        xc[row * 256 + c]       = xa;
        xc[row * 256 + 128 + c] = xm;
        s1 += xa; q1 += xa * xa;
        s2 += xm; q2 += xm * xm;
    }
    atomicAdd(&g_sum[c], (double)s1);
    atomicAdd(&g_sumsq[c], (double)q1);
    atomicAdd(&g_sum[128 + c], (double)s2);
    atomicAdd(&g_sumsq[128 + c], (double)q2);
}

// ---------------- compute scale/shift for channels [0, Cin) from g_sum/g_sumsq ----------------
__global__ void prep_kernel(const float* __restrict__ gamma,
                            const float* __restrict__ beta,
                            int Cin, double invR) {
    int k = blockIdx.x * blockDim.x + threadIdx.x;
    if (k >= Cin) return;
    double mean = g_sum[k] * invR;
    double var  = g_sumsq[k] * invR - mean * mean;
    if (var < 0.0) var = 0.0;
    double a = (double)gamma[k] * rsqrt(var + (double)EPSV);
    g_scale[k] = (float)a;
    g_shift[k] = (float)((double)beta[k] - mean * a);
}

// ---------------- analytic scale/shift for broadcast channels [128, 256) ----------------
__global__ void prep_bcast_kernel(const float* __restrict__ gamma,
                                  const float* __restrict__ beta) {
    int k = threadIdx.x;                      // 128
    double s = 0.0, sq = 0.0;
    for (int b = 0; b < Bq; b++) {
        float mf = (float)(g_avgsum[b * 128 + k] / g_masksum[b]);  // exact stored value
        double m = (double)mf;
        s  += m * (double)Nv;
        sq += m * m * (double)Nv;
    }
    double invR = 1.0 / (double)RV;
    double mean = s * invR;
    double var  = sq * invR - mean * mean;
    if (var < 0.0) var = 0.0;
    double a = (double)gamma[128 + k] * rsqrt(var + (double)EPSV);
    g_scale[128 + k] = (float)a;
    g_shift[128 + k] = (float)((double)beta[128 + k] - mean * a);
}

// ---------------- SGEMM: Cmat[R,128] = ((A*scale+shift)[R,256]) @ W + bias (+res) ----------------
__global__ void __launch_bounds__(256) gemm_kernel(const float* __restrict__ A,
                                                   const float* __restrict__ W,
                                                   const float* __restrict__ bias,
                                                   const float* __restrict__ res,
                                                   float* __restrict__ Cmat) {
    __shared__ float As[8][128];
    __shared__ float Bs[8][128];
    __shared__ float sc[256], sh[256];
    int tid = threadIdx.x;
    int row0 = blockIdx.x * 128;
    int a_r = tid >> 1, a_c = (tid & 1) * 4;
    int b_r = tid >> 5, b_c = (tid & 31) * 4;
    int ty = tid >> 4, tx = tid & 15;

    sc[tid] = g_scale[tid];
    sh[tid] = g_shift[tid];
    __syncthreads();

    float acc[8][8];
#pragma unroll
    for (int i = 0; i < 8; i++)
#pragma unroll
        for (int j = 0; j < 8; j++) acc[i][j] = 0.f;

    const float* Aptr = A + (size_t)row0 * 256;
    for (int k0 = 0; k0 < 256; k0 += 8) {
        float4 av = *(const float4*)(Aptr + a_r * 256 + k0 + a_c);
        int kk = k0 + a_c;
        As[a_c + 0][a_r] = av.x * sc[kk + 0] + sh[kk + 0];
        As[a_c + 1][a_r] = av.y * sc[kk + 1] + sh[kk + 1];
        As[a_c + 2][a_r] = av.z * sc[kk + 2] + sh[kk + 2];
        As[a_c + 3][a_r] = av.w * sc[kk + 3] + sh[kk + 3];
        *(float4*)&Bs[b_r][b_c] = *(const float4*)&W[(k0 + b_r) * 128 + b_c];
        __syncthreads();
#pragma unroll
        for (int k = 0; k < 8; k++) {
            float4 a0 = *(const float4*)&As[k][ty * 8];
            float4 a1 = *(const float4*)&As[k][ty * 8 + 4];
            float4 b0 = *(const float4*)&Bs[k][tx * 8];
            float4 b1 = *(const float4*)&Bs[k][tx * 8 + 4];
            float ar[8] = {a0.x, a0.y, a0.z, a0.w, a1.x, a1.y, a1.z, a1.w};
            float br[8] = {b0.x, b0.y, b0.z, b0.w, b1.x, b1.y, b1.z, b1.w};
#pragma unroll
            for (int i = 0; i < 8; i++)
#pragma unroll
                for (int j = 0; j < 8; j++) acc[i][j] += ar[i] * br[j];
        }
        __syncthreads();
    }

#pragma unroll
    for (int i = 0; i < 8; i++) {
        int r = row0 + ty * 8 + i;
#pragma unroll
        for (int j = 0; j < 8; j += 4) {
            int c = tx * 8 + j;
            float4 o;
            o.x = acc[i][j + 0] + bias[c + 0];
            o.y = acc[i][j + 1] + bias[c + 1];
            o.z = acc[i][j + 2] + bias[c + 2];
            o.w = acc[i][j + 3] + bias[c + 3];
            if (res) {
                const float4 rv = *(const float4*)&res[(size_t)r * 128 + c];
                o.x += rv.x; o.y += rv.y; o.z += rv.z; o.w += rv.w;
            }
            *(float4*)&Cmat[(size_t)r * 128 + c] = o;
        }
    }
}

// ---------------- avg-block: write elu(x) into xcat[:, :128] + masked sums + stats ----------------
#define AVG_RPB 50
__global__ void avg_kernel(const float* __restrict__ x,
                           const float* __restrict__ mask,
                           float* __restrict__ xc) {
    const int blocksPerBatch = Nv / AVG_RPB;   // 240
    int b = blockIdx.x / blocksPerBatch;
    int n0 = (blockIdx.x % blocksPerBatch) * AVG_RPB;
    int c = threadIdx.x;                       // 128
    float s = 0.f, ms = 0.f, s1 = 0.f, q1 = 0.f;
    for (int i = 0; i < AVG_RPB; i++) {
        int row = b * Nv + n0 + i;
        float mk = mask[row];
        float xe = elu_f(x[row * 128 + c]);
        xc[row * 256 + c] = xe;
        s  += mk * xe;
        s1 += xe;
        q1 += xe * xe;
        if (c == 0) ms += mk;
    }
    atomicAdd(&g_avgsum[b * 128 + c], (double)s);
    atomicAdd(&g_sum[c], (double)s1);
    atomicAdd(&g_sumsq[c], (double)q1);
    if (c == 0) atomicAdd(&g_masksum[b], (double)ms);
}

// ---------------- broadcast avg into xcat[:, 128:256] ----------------
__global__ void bcast_kernel(float* __restrict__ xc) {
    int idx = blockIdx.x * blockDim.x + threadIdx.x;
    if (idx >= RV * C) return;
    int r = idx >> 7, c = idx & 127;
    int b = r / Nv;
    xc[r * 256 + 128 + c] = (float)(g_avgsum[b * 128 + c] / g_masksum[b]);
}

// ---------------- final conv stats over elu(f) ----------------
__global__ void fstats_kernel(const float* __restrict__ x, int rowsPerBlock) {
    int c = threadIdx.x;                       // 128
    int r0 = blockIdx.x * rowsPerBlock;
    float s = 0.f, sq = 0.f;
    for (int r = r0; r < r0 + rowsPerBlock; r++) {
        float xv = elu_f(x[r * 128 + c]);
        s += xv; sq += xv * xv;
    }
    atomicAdd(&g_sum[c], (double)s);
    atomicAdd(&g_sumsq[c], (double)sq);
}

// ---------------- final: out[r] = sum_k (elu(f[r,k])*sc+sh) * W2[k] + b2 ----------------
__global__ void final_kernel(const float* __restrict__ f,
                             const float* __restrict__ W2,
                             const float* __restrict__ b2,
                             float* __restrict__ out) {
    int gwarp = (blockIdx.x * blockDim.x + threadIdx.x) >> 5;
    int lane = threadIdx.x & 31;
    if (gwarp >= RF) return;
    float s = 0.f;
#pragma unroll
    for (int j = 0; j < 4; j++) {
        int k = lane + j * 32;
        float xh = elu_f(f[gwarp * 128 + k]) * g_scale[k] + g_shift[k];
        s += xh * W2[k];
    }
#pragma unroll
    for (int off = 16; off; off >>= 1) s += __shfl_down_sync(0xffffffffu, s, off);
    if (lane == 0) out[gwarp] = s + b2[0];
}

// ---------------- host orchestration ----------------
extern "C" void kernel_launch(void* const* d_in, const int* in_sizes, int n_in,
                              void* d_out, int out_size) {
    const float* inputs   = (const float*)d_in[0];
    const float* mask     = (const float*)d_in[1];
    const int*   Di_rows  = (const int*)d_in[2];
    const int*   Di_cols  = (const int*)d_in[3];
    const float* Di_vals  = (const float*)d_in[4];
    const int*   DiA_rows = (const int*)d_in[5];
    const int*   DiA_cols = (const int*)d_in[6];
    const float* DiA_vals = (const float*)d_in[7];
    const float* W1       = (const float*)d_in[8];
    const float* b1       = (const float*)d_in[9];
    const float* rn_gamma = (const float*)d_in[10];
    const float* rn_beta  = (const float*)d_in[11];
    const float* rn_W     = (const float*)d_in[12];
    const float* rn_b     = (const float*)d_in[13];
    const float* g2       = (const float*)d_in[14];
    const float* be2      = (const float*)d_in[15];
    const float* W2       = (const float*)d_in[16];
    const float* b2       = (const float*)d_in[17];
    float* out = (float*)d_out;

    float *v, *f, *msg, *xcat;
    double *sum, *sumsq, *avgsum, *masksum;
    cudaGetSymbolAddress((void**)&v, g_v);
    cudaGetSymbolAddress((void**)&f, g_f);
    cudaGetSymbolAddress((void**)&msg, g_msg);
    cudaGetSymbolAddress((void**)&xcat, g_xcat);
    cudaGetSymbolAddress((void**)&sum, g_sum);
    cudaGetSymbolAddress((void**)&sumsq, g_sumsq);
    cudaGetSymbolAddress((void**)&avgsum, g_avgsum);
    cudaGetSymbolAddress((void**)&masksum, g_masksum);

    auto clear_stats = [&]() {
        cudaMemsetAsync(sum, 0, 256 * sizeof(double), 0);
        cudaMemsetAsync(sumsq, 0, 256 * sizeof(double), 0);
    };

    // conv1 + init f = 0
    conv1_kernel<<<(RV * C) / 256, 256>>>(inputs, W1, b1);
    cudaMemsetAsync(f, 0, (size_t)RF * C * sizeof(float), 0);

    for (int i = 0; i < 16; i++) {
        const float* W0  = rn_W + (size_t)i * 2 * 256 * 128;
        const float* Wb0 = rn_b + (size_t)i * 2 * 128;
        const float* gm0 = rn_gamma + (size_t)i * 2 * 256;
        const float* bt0 = rn_beta + (size_t)i * 2 * 256;

        if ((i & 1) == 0) {
            // ---- dir block ----
            // msg_v = DiA @ f_reshaped
            cudaMemsetAsync(msg, 0, (size_t)RV * C * sizeof(float), 0);
            scatter_kernel<<<NNZ / 2, 256>>>(DiA_rows, DiA_cols, DiA_vals, f, msg,
                                             FN * C, Nv * C);
            clear_stats();
            elucat_stats_kernel<<<RV / EC_ROWS, 128>>>(v, msg, xcat);
            prep_kernel<<<1, 256>>>(gm0, bt0, 256, 1.0 / RV);
            gemm_kernel<<<RV / 128, 256>>>(xcat, W0, Wb0, v, v);       // v += conv

            // msg_f = Di @ v_out_reshaped
            cudaMemsetAsync(msg, 0, (size_t)RF * C * sizeof(float), 0);
            scatter_kernel<<<NNZ / 2, 256>>>(Di_rows, Di_cols, Di_vals, v, msg,
                                             Nv * C, FN * C);
            clear_stats();
            elucat_stats_kernel<<<RF / EC_ROWS, 128>>>(f, msg, xcat);
            prep_kernel<<<1, 256>>>(gm0 + 256, bt0 + 256, 256, 1.0 / RF);
            gemm_kernel<<<RF / 128, 256>>>(xcat, W0 + 256 * 128, Wb0 + 128,
                                           nullptr, f);                // f = conv
        } else {
            // ---- avg block ----
            // j = 0: x1 = conv(concat(elu(v), avg)) -> msg (temp)
            clear_stats();
            cudaMemsetAsync(avgsum, 0, Bq * C * sizeof(double), 0);
            cudaMemsetAsync(masksum, 0, Bq * sizeof(double), 0);
            avg_kernel<<<Bq * (Nv / AVG_RPB), 128>>>(v, mask, xcat);
            bcast_kernel<<<(RV * C) / 256, 256>>>(xcat);
            prep_kernel<<<1, 128>>>(gm0, bt0, 128, 1.0 / RV);
            prep_bcast_kernel<<<1, 128>>>(gm0, bt0);
            gemm_kernel<<<RV / 128, 256>>>(xcat, W0, Wb0, nullptr, msg);

            // j = 1: v = conv(concat(elu(x1), avg)) + v
            clear_stats();
            cudaMemsetAsync(avgsum, 0, Bq * C * sizeof(double), 0);
            cudaMemsetAsync(masksum, 0, Bq * sizeof(double), 0);
            avg_kernel<<<Bq * (Nv / AVG_RPB), 128>>>(msg, mask, xcat);
            bcast_kernel<<<(RV * C) / 256, 256>>>(xcat);
            prep_kernel<<<1, 128>>>(gm0 + 256, bt0 + 256, 128, 1.0 / RV);
            prep_bcast_kernel<<<1, 128>>>(gm0 + 256, bt0 + 256);
            gemm_kernel<<<RV / 128, 256>>>(xcat, W0 + 256 * 128, Wb0 + 128, v, v);
        }
    }

    // final conv: stats over elu(f)[RF, 128], prep, dot
    clear_stats();
    fstats_kernel<<<RF / 128, 128>>>(f, 128);
    prep_kernel<<<1, 128>>>(g2, be2, 128, 1.0 / RF);
    final_kernel<<<(RF + 7) / 8, 256>>>(f, W2, b2, out);
}

// round 3
// speedup vs baseline: 1.4179x; 1.4179x over previous
#include <cuda_runtime.h>
#include <math.h>

#define Bq 4
#define Nv 12000
#define FN 24000
#define C 128
#define NNZ (48 * FN)     // 1,152,000
#define EPSV 1e-5f

#define RV (Bq * Nv)      // 48000 vertex rows
#define RF (Bq * FN)      // 96000 face rows

#define BINS 98304        // 96 * 1024 (covers 96000 rows)
#define EC_ROWS 64

// ---------------- scratch (device globals: allocation-free) ----------------
__device__ float  g_v[RV * C];
__device__ float  g_f[RF * C];
__device__ float  g_msg[RF * C];
__device__ double g_sum[256];
__device__ double g_sumsq[256];
__device__ float  g_scale[256];
__device__ float  g_shift[256];
__device__ double g_avgsum[Bq * C];
__device__ double g_masksum[Bq];
__device__ float  g_bb[Bq * C];         // per-batch folded bias (avg blocks)

// CSR build scratch
__device__ int g_cnt[BINS];
__device__ int g_incl[BINS];
__device__ int g_bsum[96];
__device__ int g_cursor[BINS];
__device__ int g_startA[BINS + 1];      // DiA: 48000 rows
__device__ int g_startB[BINS + 1];      // Di : 96000 rows
__device__ int g_permA[NNZ];
__device__ int g_permB[NNZ];

__device__ __forceinline__ float elu_f(float x) {
    return x > 0.f ? x : expm1f(x);
}

// ================= CSR build =================
__global__ void hist_kernel(const int* __restrict__ rows) {
    int i = blockIdx.x * blockDim.x + threadIdx.x;
    if (i < NNZ) atomicAdd(&g_cnt[rows[i]], 1);
}

__global__ void scan_block_kernel() {
    __shared__ int sd[1024];
    int t = threadIdx.x;
    int gid = blockIdx.x * 1024 + t;
    sd[t] = g_cnt[gid];
    __syncthreads();
    for (int off = 1; off < 1024; off <<= 1) {
        int add = (t >= off) ? sd[t - off] : 0;
        __syncthreads();
        sd[t] += add;
        __syncthreads();
    }
    g_incl[gid] = sd[t];
    if (t == 1023) g_bsum[blockIdx.x] = sd[1023];
}

__global__ void scan_top_kernel() {
    if (threadIdx.x == 0) {
        int run = 0;
        for (int b = 0; b < 96; b++) { int tt = g_bsum[b]; g_bsum[b] = run; run += tt; }
    }
}

__global__ void scan_finish_kernel(int* __restrict__ start) {
    int t = threadIdx.x;
    int gid = blockIdx.x * 1024 + t;
    int excl = g_incl[gid] - g_cnt[gid] + g_bsum[blockIdx.x];
    start[gid] = excl;
    g_cursor[gid] = excl;
    if (gid == BINS - 1) start[BINS] = excl + g_cnt[gid];
}

__global__ void fill_kernel(const int* __restrict__ rows, int* __restrict__ perm) {
    int i = blockIdx.x * blockDim.x + threadIdx.x;
    if (i >= NNZ) return;
    int pos = atomicAdd(&g_cursor[rows[i]], 1);
    perm[pos] = i;
}

// ================= SpMM (CSR, atomic-free) =================
// out[b, r*32 + k] = sum_{e in row r} vals[e] * in[b, cols[e]*32 + k]
// block: 128 threads = 4 rows x 32 lanes; lane -> (b = lane>>3, k4 = lane&7)
__global__ void spmm_kernel(const int* __restrict__ start,
                            const int* __restrict__ perm,
                            const int* __restrict__ cols,
                            const float* __restrict__ vals,
                            const float* __restrict__ in, int inStride,
                            float* __restrict__ out, int outStride) {
    int t = threadIdx.x;
    int r = blockIdx.x * 4 + (t >> 5);
    int lane = t & 31;
    int b = lane >> 3, k4 = lane & 7;
    int s = start[r], e = start[r + 1];
    float4 acc = make_float4(0.f, 0.f, 0.f, 0.f);
    const float* inb = in + (size_t)b * inStride;
    for (int i = s; i < e; i++) {
        int eid = perm[i];
        float val = vals[eid];
        int c = cols[eid];
        float4 q = *(const float4*)&inb[c * 32 + k4 * 4];
        acc.x += val * q.x; acc.y += val * q.y;
        acc.z += val * q.z; acc.w += val * q.w;
    }
    *(float4*)&out[(size_t)b * outStride + r * 32 + k4 * 4] = acc;
}

// ================= conv1 =================
__global__ void conv1_kernel(const float* __restrict__ in,
                             const float* __restrict__ W1,
                             const float* __restrict__ b1) {
    int idx = blockIdx.x * blockDim.x + threadIdx.x;
    if (idx >= RV * C) return;
    int r = idx >> 7, c = idx & 127;
    float x0 = in[r * 3 + 0], x1 = in[r * 3 + 1], x2 = in[r * 3 + 2];
    g_v[idx] = x0 * W1[c] + x1 * W1[128 + c] + x2 * W1[256 + c] + b1[c];
}

// ================= stats over elu of two sources (dir blocks) =================
__global__ void stats2_kernel(const float* __restrict__ x0,
                              const float* __restrict__ x1) {
    int c = threadIdx.x;                      // 128
    int r0 = blockIdx.x * EC_ROWS;
    float s1 = 0.f, q1 = 0.f, s2 = 0.f, q2 = 0.f;
    for (int i = 0; i < EC_ROWS; i++) {
        int row = r0 + i;
        float xa = elu_f(x0[(size_t)row * 128 + c]);
        float xm = elu_f(x1[(size_t)row * 128 + c]);
        s1 += xa; q1 += xa * xa;
        s2 += xm; q2 += xm * xm;
    }
    atomicAdd(&g_sum[c], (double)s1);
    atomicAdd(&g_sumsq[c], (double)q1);
    atomicAdd(&g_sum[128 + c], (double)s2);
    atomicAdd(&g_sumsq[128 + c], (double)q2);
}

// ================= scale/shift prep =================
__global__ void prep_kernel(const float* __restrict__ gamma,
                            const float* __restrict__ beta,
                            int Cin, double invR) {
    int k = blockIdx.x * blockDim.x + threadIdx.x;
    if (k >= Cin) return;
    double mean = g_sum[k] * invR;
    double var  = g_sumsq[k] * invR - mean * mean;
    if (var < 0.0) var = 0.0;
    double a = (double)gamma[k] * rsqrt(var + (double)EPSV);
    g_scale[k] = (float)a;
    g_shift[k] = (float)((double)beta[k] - mean * a);
}

__global__ void prep_bcast_kernel(const float* __restrict__ gamma,
                                  const float* __restrict__ beta) {
    int k = threadIdx.x;                      // 128
    double s = 0.0, sq = 0.0;
    for (int b = 0; b < Bq; b++) {
        float mf = (float)(g_avgsum[b * 128 + k] / g_masksum[b]);
        double m = (double)mf;
        s  += m * (double)Nv;
        sq += m * m * (double)Nv;
    }
    double invR = 1.0 / (double)RV;
    double mean = s * invR;
    double var  = sq * invR - mean * mean;
    if (var < 0.0) var = 0.0;
    double a = (double)gamma[128 + k] * rsqrt(var + (double)EPSV);
    g_scale[128 + k] = (float)a;
    g_shift[128 + k] = (float)((double)beta[128 + k] - mean * a);
}

// per-batch folded bias from broadcast channels: bb[b][c] = sum_k xh2[b,k]*W[128+k][c]
__global__ void bb_kernel(const float* __restrict__ W) {
    int b = blockIdx.x, c = threadIdx.x;
    float acc = 0.f;
    for (int k = 0; k < 128; k++) {
        float af = (float)(g_avgsum[b * 128 + k] / g_masksum[b]);
        float xh = af * g_scale[128 + k] + g_shift[128 + k];
        acc += xh * W[(128 + k) * 128 + c];
    }
    g_bb[b * 128 + c] = acc;
}

// ================= GEMM =================
// out[M,128] = (elu(A)*scale+shift)[M,KD] @ W[KD,128] + bias (+ res) (+ bb per batch)
// KD=256: A channels 0..127 from A0, 128..255 from A1 (both [M,128] row-major).
// KD=128 (AVG): A0 only; bb[b][c] added in epilogue.
template <int KD, bool AVG>
__global__ void __launch_bounds__(256) gemm_kernel(
    const float* __restrict__ A0, const float* __restrict__ A1,
    const float* __restrict__ W, const float* __restrict__ bias,
    const float* __restrict__ res, float* __restrict__ out) {
    __shared__ float As[2][16][128];
    __shared__ float Bs[2][16][128];
    __shared__ float sc[KD], sh[KD];
    const int tid = threadIdx.x;
    const int row0 = blockIdx.x * 128;

    if (tid < KD) { sc[tid] = g_scale[tid]; sh[tid] = g_shift[tid]; }

    const int arow = tid >> 1;            // 0..127
    const int akb  = (tid & 1) * 8;       // 0 or 8
    const int bkr  = tid >> 4;            // 0..15
    const int bcc  = (tid & 15) * 8;
    const int ty = tid >> 4, tx = tid & 15;
    const int NCH = KD / 16;

    float4 areg[2], breg[2];

    auto loadAB = [&](int k0) {
#pragma unroll
        for (int q = 0; q < 2; q++) {
            int k = k0 + akb + q * 4;
            const float* src;
            if (KD == 256 && k >= 128)
                src = A1 + (size_t)(row0 + arow) * 128 + (k - 128);
            else
                src = A0 + (size_t)(row0 + arow) * 128 + k;
            areg[q] = *(const float4*)src;
            breg[q] = *(const float4*)&W[(size_t)(k0 + bkr) * 128 + bcc + q * 4];
        }
    };
    auto storeAB = [&](int buf, int k0) {
#pragma unroll
        for (int q = 0; q < 2; q++) {
            float vv[4] = {areg[q].x, areg[q].y, areg[q].z, areg[q].w};
#pragma unroll
            for (int j = 0; j < 4; j++) {
                int kl = akb + q * 4 + j;
                float x = vv[j];
                x = x > 0.f ? x : expm1f(x);
                As[buf][kl][arow] = x * sc[k0 + kl] + sh[k0 + kl];
            }
            *(float4*)&Bs[buf][bkr][bcc + q * 4] = breg[q];
        }
    };

    float acc[8][8];
#pragma unroll
    for (int i = 0; i < 8; i++)
#pragma unroll
        for (int j = 0; j < 8; j++) acc[i][j] = 0.f;

    loadAB(0);
    __syncthreads();            // sc/sh ready
    storeAB(0, 0);
    __syncthreads();

    for (int ch = 0; ch < NCH; ch++) {
        int nxt = ch + 1;
        if (nxt < NCH) loadAB(nxt * 16);
        int buf = ch & 1;
#pragma unroll
        for (int kk = 0; kk < 16; kk++) {
            float4 a0 = *(const float4*)&As[buf][kk][ty * 8];
            float4 a1 = *(const float4*)&As[buf][kk][ty * 8 + 4];
            float4 b0 = *(const float4*)&Bs[buf][kk][tx * 8];
            float4 b1 = *(const float4*)&Bs[buf][kk][tx * 8 + 4];
            float ar[8] = {a0.x, a0.y, a0.z, a0.w, a1.x, a1.y, a1.z, a1.w};
            float br[8] = {b0.x, b0.y, b0.z, b0.w, b1.x, b1.y, b1.z, b1.w};
#pragma unroll
            for (int i = 0; i < 8; i++)
#pragma unroll
                for (int j = 0; j < 8; j++) acc[i][j] += ar[i] * br[j];
        }
        if (nxt < NCH) {
            __syncthreads();
            storeAB(nxt & 1, nxt * 16);
            __syncthreads();
        }
    }

#pragma unroll
    for (int i = 0; i < 8; i++) {
        int r = row0 + ty * 8 + i;
        int rb = AVG ? (r / Nv) : 0;
#pragma unroll
        for (int j = 0; j < 8; j += 4) {
            int c = tx * 8 + j;
            float4 o;
            o.x = acc[i][j + 0] + bias[c + 0];
            o.y = acc[i][j + 1] + bias[c + 1];
            o.z = acc[i][j + 2] + bias[c + 2];
            o.w = acc[i][j + 3] + bias[c + 3];
            if (AVG) {
                const float4 bv = *(const float4*)&g_bb[rb * 128 + c];
                o.x += bv.x; o.y += bv.y; o.z += bv.z; o.w += bv.w;
            }
            if (res) {
                const float4 rv = *(const float4*)&res[(size_t)r * 128 + c];
                o.x += rv.x; o.y += rv.y; o.z += rv.z; o.w += rv.w;
            }
            *(float4*)&out[(size_t)r * 128 + c] = o;
        }
    }
}

// ================= avg-block: masked sums + stats (no feature writes) ============
#define AVG_RPB 50
__global__ void avg_kernel(const float* __restrict__ x,
                           const float* __restrict__ mask) {
    const int blocksPerBatch = Nv / AVG_RPB;   // 240
    int b = blockIdx.x / blocksPerBatch;
    int n0 = (blockIdx.x % blocksPerBatch) * AVG_RPB;
    int c = threadIdx.x;                       // 128
    float s = 0.f, ms = 0.f, s1 = 0.f, q1 = 0.f;
    for (int i = 0; i < AVG_RPB; i++) {
        int row = b * Nv + n0 + i;
        float mk = mask[row];
        float xe = elu_f(x[(size_t)row * 128 + c]);
        s  += mk * xe;
        s1 += xe;
        q1 += xe * xe;
        if (c == 0) ms += mk;
    }
    atomicAdd(&g_avgsum[b * 128 + c], (double)s);
    atomicAdd(&g_sum[c], (double)s1);
    atomicAdd(&g_sumsq[c], (double)q1);
    if (c == 0) atomicAdd(&g_masksum[b], (double)ms);
}

// ================= final conv =================
__global__ void fstats_kernel(const float* __restrict__ x, int rowsPerBlock) {
    int c = threadIdx.x;                       // 128
    int r0 = blockIdx.x * rowsPerBlock;
    float s = 0.f, sq = 0.f;
    for (int r = r0; r < r0 + rowsPerBlock; r++) {
        float xv = elu_f(x[(size_t)r * 128 + c]);
        s += xv; sq += xv * xv;
    }
    atomicAdd(&g_sum[c], (double)s);
    atomicAdd(&g_sumsq[c], (double)sq);
}

__global__ void final_kernel(const float* __restrict__ f,
                             const float* __restrict__ W2,
                             const float* __restrict__ b2,
                             float* __restrict__ out) {
    int gwarp = (blockIdx.x * blockDim.x + threadIdx.x) >> 5;
    int lane = threadIdx.x & 31;
    if (gwarp >= RF) return;
    float s = 0.f;
#pragma unroll
    for (int j = 0; j < 4; j++) {
        int k = lane + j * 32;
        float xh = elu_f(f[(size_t)gwarp * 128 + k]) * g_scale[k] + g_shift[k];
        s += xh * W2[k];
    }
#pragma unroll
    for (int off = 16; off; off >>= 1) s += __shfl_down_sync(0xffffffffu, s, off);
    if (lane == 0) out[gwarp] = s + b2[0];
}

// ================= host orchestration =================
extern "C" void kernel_launch(void* const* d_in, const int* in_sizes, int n_in,
                              void* d_out, int out_size) {
    const float* inputs   = (const float*)d_in[0];
    const float* mask     = (const float*)d_in[1];
    const int*   Di_rows  = (const int*)d_in[2];
    const int*   Di_cols  = (const int*)d_in[3];
    const float* Di_vals  = (const float*)d_in[4];
    const int*   DiA_rows = (const int*)d_in[5];
    const int*   DiA_cols = (const int*)d_in[6];
    const float* DiA_vals = (const float*)d_in[7];
    const float* W1       = (const float*)d_in[8];
    const float* b1       = (const float*)d_in[9];
    const float* rn_gamma = (const float*)d_in[10];
    const float* rn_beta  = (const float*)d_in[11];
    const float* rn_W     = (const float*)d_in[12];
    const float* rn_b     = (const float*)d_in[13];
    const float* g2       = (const float*)d_in[14];
    const float* be2      = (const float*)d_in[15];
    const float* W2       = (const float*)d_in[16];
    const float* b2       = (const float*)d_in[17];
    float* out = (float*)d_out;

    float *v, *f, *msg;
    double *sum, *sumsq, *avgsum, *masksum;
    int *cnt, *startA, *startB, *permA, *permB;
    cudaGetSymbolAddress((void**)&v, g_v);
    cudaGetSymbolAddress((void**)&f, g_f);
    cudaGetSymbolAddress((void**)&msg, g_msg);
    cudaGetSymbolAddress((void**)&sum, g_sum);
    cudaGetSymbolAddress((void**)&sumsq, g_sumsq);
    cudaGetSymbolAddress((void**)&avgsum, g_avgsum);
    cudaGetSymbolAddress((void**)&masksum, g_masksum);
    cudaGetSymbolAddress((void**)&cnt, g_cnt);
    cudaGetSymbolAddress((void**)&startA, g_startA);
    cudaGetSymbolAddress((void**)&startB, g_startB);
    cudaGetSymbolAddress((void**)&permA, g_permA);
    cudaGetSymbolAddress((void**)&permB, g_permB);

    auto clear_stats = [&]() {
        cudaMemsetAsync(sum, 0, 256 * sizeof(double), 0);
        cudaMemsetAsync(sumsq, 0, 256 * sizeof(double), 0);
    };
    auto build_csr = [&](const int* rows, int* start, int* perm) {
        cudaMemsetAsync(cnt, 0, BINS * sizeof(int), 0);
        hist_kernel<<<NNZ / 256, 256>>>(rows);
        scan_block_kernel<<<96, 1024>>>();
        scan_top_kernel<<<1, 32>>>();
        scan_finish_kernel<<<96, 1024>>>(start);
        fill_kernel<<<NNZ / 256, 256>>>(rows, perm);
    };

    // CSR for both sparse operators (pattern fixed; rebuilt each replay)
    build_csr(DiA_rows, startA, permA);
    build_csr(Di_rows, startB, permB);

    // conv1 + init f = 0
    conv1_kernel<<<(RV * C) / 256, 256>>>(inputs, W1, b1);
    cudaMemsetAsync(f, 0, (size_t)RF * C * sizeof(float), 0);

    for (int i = 0; i < 16; i++) {
        const float* W0  = rn_W + (size_t)i * 2 * 256 * 128;
        const float* Wb0 = rn_b + (size_t)i * 2 * 128;
        const float* gm0 = rn_gamma + (size_t)i * 2 * 256;
        const float* bt0 = rn_beta + (size_t)i * 2 * 256;

        if ((i & 1) == 0) {
            // ---- dir block ----
            // msg_v = DiA @ f_reshaped   (48000 output rows)
            spmm_kernel<<<RV / 4, 128>>>(startA, permA, DiA_cols, DiA_vals,
                                         f, FN * C, msg, Nv * C);
            clear_stats();
            stats2_kernel<<<RV / EC_ROWS, 128>>>(v, msg);
            prep_kernel<<<1, 256>>>(gm0, bt0, 256, 1.0 / RV);
            gemm_kernel<256, false><<<RV / 128, 256>>>(v, msg, W0, Wb0, v, v);

            // msg_f = Di @ v_out_reshaped  (96000 output rows)
            spmm_kernel<<<RF / 4, 128>>>(startB, permB, Di_cols, Di_vals,
                                         v, Nv * C, msg, FN * C);
            clear_stats();
            stats2_kernel<<<RF / EC_ROWS, 128>>>(f, msg);
            prep_kernel<<<1, 256>>>(gm0 + 256, bt0 + 256, 256, 1.0 / RF);
            gemm_kernel<256, false><<<RF / 128, 256>>>(f, msg, W0 + 256 * 128,
                                                       Wb0 + 128, nullptr, f);
        } else {
            // ---- avg block ----
            // j = 0: x1 = conv(concat(elu(v), avg)) -> msg
            clear_stats();
            cudaMemsetAsync(avgsum, 0, Bq * C * sizeof(double), 0);
            cudaMemsetAsync(masksum, 0, Bq * sizeof(double), 0);
            avg_kernel<<<Bq * (Nv / AVG_RPB), 128>>>(v, mask);
            prep_kernel<<<1, 128>>>(gm0, bt0, 128, 1.0 / RV);
            prep_bcast_kernel<<<1, 128>>>(gm0, bt0);
            bb_kernel<<<Bq, 128>>>(W0);
            gemm_kernel<128, true><<<RV / 128, 256>>>(v, nullptr, W0, Wb0,
                                                      nullptr, msg);

            // j = 1: v = conv(concat(elu(x1), avg)) + v
            clear_stats();
            cudaMemsetAsync(avgsum, 0, Bq * C * sizeof(double), 0);
            cudaMemsetAsync(masksum, 0, Bq * sizeof(double), 0);
            avg_kernel<<<Bq * (Nv / AVG_RPB), 128>>>(msg, mask);
            prep_kernel<<<1, 128>>>(gm0 + 256, bt0 + 256, 128, 1.0 / RV);
            prep_bcast_kernel<<<1, 128>>>(gm0 + 256, bt0 + 256);
            bb_kernel<<<Bq, 128>>>(W0 + 256 * 128);
            gemm_kernel<128, true><<<RV / 128, 256>>>(msg, nullptr,
                                                      W0 + 256 * 128, Wb0 + 128,
                                                      v, v);
        }
    }

    // final conv: stats over elu(f)[RF, 128], prep, dot
    clear_stats();
    fstats_kernel<<<RF / 128, 128>>>(f, 128);
    prep_kernel<<<1, 128>>>(g2, be2, 128, 1.0 / RF);
    final_kernel<<<(RF + 7) / 8, 256>>>(f, W2, b2, out);
}

// round 4
// speedup vs baseline: 2.2636x; 1.5965x over previous
#include <cuda_runtime.h>
#include <math.h>

#define Bq 4
#define Nv 12000
#define FN 24000
#define C 128
#define NNZ (48 * FN)     // 1,152,000
#define EPSV 1e-5f

#define RV (Bq * Nv)      // 48000 vertex rows
#define RF (Bq * FN)      // 96000 face rows

#define BINS 98304        // 96 * 1024 (covers 96000 rows)
#define EC_ROWS 64

// ---------------- scratch (device globals: allocation-free) ----------------
__device__ float  g_v[RV * C];
__device__ float  g_f[RF * C];
__device__ float  g_msg[RF * C];
__device__ double g_sum[256];
__device__ double g_sumsq[256];
__device__ float  g_scale[256];
__device__ float  g_shift[256];
__device__ double g_avgsum[Bq * C];
__device__ double g_masksum[Bq];
__device__ float  g_bb[Bq * C];         // per-batch folded bias (avg blocks)

// CSR build scratch
__device__ int    g_cnt[BINS];
__device__ int    g_incl[BINS];
__device__ int    g_bsum[96];
__device__ int    g_cursor[BINS];
__device__ int    g_startA[BINS + 1];   // DiA: 48000 rows
__device__ int    g_startB[BINS + 1];   // Di : 96000 rows
__device__ float2 g_edgeA[NNZ];         // (val, bitcast col), row-sorted
__device__ float2 g_edgeB[NNZ];

__device__ __forceinline__ float elu_f(float x) {
    return x > 0.f ? x : expm1f(x);
}

// ================= CSR build =================
__global__ void hist_kernel(const int* __restrict__ rows) {
    int i = blockIdx.x * blockDim.x + threadIdx.x;
    if (i < NNZ) atomicAdd(&g_cnt[rows[i]], 1);
}

__global__ void scan_block_kernel() {
    __shared__ int sd[1024];
    int t = threadIdx.x;
    int gid = blockIdx.x * 1024 + t;
    sd[t] = g_cnt[gid];
    __syncthreads();
    for (int off = 1; off < 1024; off <<= 1) {
        int add = (t >= off) ? sd[t - off] : 0;
        __syncthreads();
        sd[t] += add;
        __syncthreads();
    }
    g_incl[gid] = sd[t];
    if (t == 1023) g_bsum[blockIdx.x] = sd[1023];
}

__global__ void scan_top_kernel() {
    if (threadIdx.x == 0) {
        int run = 0;
        for (int b = 0; b < 96; b++) { int tt = g_bsum[b]; g_bsum[b] = run; run += tt; }
    }
}

__global__ void scan_finish_kernel(int* __restrict__ start) {
    int t = threadIdx.x;
    int gid = blockIdx.x * 1024 + t;
    int excl = g_incl[gid] - g_cnt[gid] + g_bsum[blockIdx.x];
    start[gid] = excl;
    g_cursor[gid] = excl;
    if (gid == BINS - 1) start[BINS] = excl + g_cnt[gid];
}

__global__ void fill_kernel(const int* __restrict__ rows,
                            const int* __restrict__ cols,
                            const float* __restrict__ vals,
                            float2* __restrict__ edges) {
    int i = blockIdx.x * blockDim.x + threadIdx.x;
    if (i >= NNZ) return;
    int pos = atomicAdd(&g_cursor[rows[i]], 1);
    edges[pos] = make_float2(vals[i], __int_as_float(cols[i]));
}

// ================= SpMM (CSR, atomic-free) =================
// out[b, r*32 + k] = sum_{e in row r} val_e * in[b, col_e*32 + k]
// block: 128 threads = 4 rows x 32 lanes; lane -> (b = lane>>3, k4 = lane&7)
__global__ void spmm_kernel(const int* __restrict__ start,
                            const float2* __restrict__ edges,
                            const float* __restrict__ in, int inStride,
                            float* __restrict__ out, int outStride) {
    int t = threadIdx.x;
    int r = blockIdx.x * 4 + (t >> 5);
    int lane = t & 31;
    int b = lane >> 3, k4 = lane & 7;
    int s = start[r], e = start[r + 1];
    float4 acc = make_float4(0.f, 0.f, 0.f, 0.f);
    const float* inb = in + (size_t)b * inStride;
    for (int i = s; i < e; i++) {
        float2 ed = edges[i];
        int c = __float_as_int(ed.y);
        float4 q = *(const float4*)&inb[c * 32 + k4 * 4];
        acc.x = fmaf(ed.x, q.x, acc.x);
        acc.y = fmaf(ed.x, q.y, acc.y);
        acc.z = fmaf(ed.x, q.z, acc.z);
        acc.w = fmaf(ed.x, q.w, acc.w);
    }
    *(float4*)&out[(size_t)b * outStride + r * 32 + k4 * 4] = acc;
}

// ================= conv1 =================
__global__ void conv1_kernel(const float* __restrict__ in,
                             const float* __restrict__ W1,
                             const float* __restrict__ b1) {
    int idx = blockIdx.x * blockDim.x + threadIdx.x;
    if (idx >= RV * C) return;
    int r = idx >> 7, c = idx & 127;
    float x0 = in[r * 3 + 0], x1 = in[r * 3 + 1], x2 = in[r * 3 + 2];
    g_v[idx] = x0 * W1[c] + x1 * W1[128 + c] + x2 * W1[256 + c] + b1[c];
}

// ================= stats over elu of two sources (dir blocks) =================
__global__ void stats2_kernel(const float* __restrict__ x0,
                              const float* __restrict__ x1) {
    int c = threadIdx.x;                      // 128
    int r0 = blockIdx.x * EC_ROWS;
    float s1 = 0.f, q1 = 0.f, s2 = 0.f, q2 = 0.f;
    for (int i = 0; i < EC_ROWS; i++) {
        int row = r0 + i;
        float xa = elu_f(x0[(size_t)row * 128 + c]);
        float xm = elu_f(x1[(size_t)row * 128 + c]);
        s1 += xa; q1 += xa * xa;
        s2 += xm; q2 += xm * xm;
    }
    atomicAdd(&g_sum[c], (double)s1);
    atomicAdd(&g_sumsq[c], (double)q1);
    atomicAdd(&g_sum[128 + c], (double)s2);
    atomicAdd(&g_sumsq[128 + c], (double)q2);
}

// ================= scale/shift prep =================
__global__ void prep_kernel(const float* __restrict__ gamma,
                            const float* __restrict__ beta,
                            int Cin, double invR) {
    int k = blockIdx.x * blockDim.x + threadIdx.x;
    if (k >= Cin) return;
    double mean = g_sum[k] * invR;
    double var  = g_sumsq[k] * invR - mean * mean;
    if (var < 0.0) var = 0.0;
    double a = (double)gamma[k] * rsqrt(var + (double)EPSV);
    g_scale[k] = (float)a;
    g_shift[k] = (float)((double)beta[k] - mean * a);
}

__global__ void prep_bcast_kernel(const float* __restrict__ gamma,
                                  const float* __restrict__ beta) {
    int k = threadIdx.x;                      // 128
    double s = 0.0, sq = 0.0;
    for (int b = 0; b < Bq; b++) {
        float mf = (float)(g_avgsum[b * 128 + k] / g_masksum[b]);
        double m = (double)mf;
        s  += m * (double)Nv;
        sq += m * m * (double)Nv;
    }
    double invR = 1.0 / (double)RV;
    double mean = s * invR;
    double var  = sq * invR - mean * mean;
    if (var < 0.0) var = 0.0;
    double a = (double)gamma[128 + k] * rsqrt(var + (double)EPSV);
    g_scale[128 + k] = (float)a;
    g_shift[128 + k] = (float)((double)beta[128 + k] - mean * a);
}

// per-batch folded bias: bb[b][c] = sum_k xh2[b,k]*W[128+k][c]
__global__ void bb_kernel(const float* __restrict__ W) {
    int b = blockIdx.x, c = threadIdx.x;
    float acc = 0.f;
    for (int k = 0; k < 128; k++) {
        float af = (float)(g_avgsum[b * 128 + k] / g_masksum[b]);
        float xh = af * g_scale[128 + k] + g_shift[128 + k];
        acc += xh * W[(128 + k) * 128 + c];
    }
    g_bb[b * 128 + c] = acc;
}

// ================= GEMM (conflict-free fragment mapping) =================
// out[M,128] = (elu(A)*scale+shift)[M,KD] @ W[KD,128] + bias (+ res) (+ bb per batch)
// KD=256: A channels 0..127 from A0, 128..255 from A1.
// Thread (ty,tx) owns rows {ty*4+il, ty*4+64+il}, cols {tx*4+jl, tx*4+64+jl}.
template <int KD, bool AVG>
__global__ void __launch_bounds__(256) gemm_kernel(
    const float* __restrict__ A0, const float* __restrict__ A1,
    const float* __restrict__ W, const float* __restrict__ bias,
    const float* __restrict__ res, float* __restrict__ out) {
    __shared__ float As[2][16][128];
    __shared__ float Bs[2][16][128];
    __shared__ float sc[KD], sh[KD];
    const int tid = threadIdx.x;
    const int row0 = blockIdx.x * 128;

    if (tid < KD) { sc[tid] = g_scale[tid]; sh[tid] = g_shift[tid]; }

    const int arow = tid >> 1;            // 0..127
    const int akb  = (tid & 1) * 8;       // 0 or 8
    const int bkr  = tid >> 4;            // 0..15
    const int bcx  = (tid & 15) * 4;      // 0..60
    const int ty = tid >> 4, tx = tid & 15;
    const int NCH = KD / 16;

    float4 areg[2], breg[2];

    auto loadAB = [&](int k0) {
#pragma unroll
        for (int q = 0; q < 2; q++) {
            int k = k0 + akb + q * 4;
            const float* src;
            if (KD == 256 && k >= 128)
                src = A1 + (size_t)(row0 + arow) * 128 + (k - 128);
            else
                src = A0 + (size_t)(row0 + arow) * 128 + k;
            areg[q] = *(const float4*)src;
            breg[q] = *(const float4*)&W[(size_t)(k0 + bkr) * 128 + bcx + q * 64];
        }
    };
    auto storeAB = [&](int buf, int k0) {
#pragma unroll
        for (int q = 0; q < 2; q++) {
            float vv[4] = {areg[q].x, areg[q].y, areg[q].z, areg[q].w};
#pragma unroll
            for (int j = 0; j < 4; j++) {
                int kl = akb + q * 4 + j;
                float x = vv[j];
                x = x > 0.f ? x : expm1f(x);
                As[buf][kl][arow] = fmaf(x, sc[k0 + kl], sh[k0 + kl]);
            }
            *(float4*)&Bs[buf][bkr][bcx + q * 64] = breg[q];
        }
    };

    float acc[8][8];
#pragma unroll
    for (int i = 0; i < 8; i++)
#pragma unroll
        for (int j = 0; j < 8; j++) acc[i][j] = 0.f;

    loadAB(0);
    __syncthreads();            // sc/sh ready
    storeAB(0, 0);
    __syncthreads();

    for (int ch = 0; ch < NCH; ch++) {
        int nxt = ch + 1;
        if (nxt < NCH) loadAB(nxt * 16);
        int buf = ch & 1;
#pragma unroll
        for (int kk = 0; kk < 16; kk++) {
            float4 a0 = *(const float4*)&As[buf][kk][ty * 4];
            float4 a1 = *(const float4*)&As[buf][kk][ty * 4 + 64];
            float4 b0 = *(const float4*)&Bs[buf][kk][tx * 4];
            float4 b1 = *(const float4*)&Bs[buf][kk][tx * 4 + 64];
            float av[8] = {a0.x, a0.y, a0.z, a0.w, a1.x, a1.y, a1.z, a1.w};
            float bv[8] = {b0.x, b0.y, b0.z, b0.w, b1.x, b1.y, b1.z, b1.w};
#pragma unroll
            for (int i = 0; i < 8; i++)
#pragma unroll
                for (int j = 0; j < 8; j++)
                    acc[i][j] = fmaf(av[i], bv[j], acc[i][j]);
        }
        if (nxt < NCH) {
            __syncthreads();
            storeAB(nxt & 1, nxt * 16);
            __syncthreads();
        }
    }

#pragma unroll
    for (int i = 0; i < 8; i++) {
        int r = row0 + ty * 4 + (i & 3) + (i >> 2) * 64;
        int rb = AVG ? (r / Nv) : 0;
#pragma unroll
        for (int jh = 0; jh < 2; jh++) {
            int c = tx * 4 + jh * 64;
            float4 o;
            o.x = acc[i][jh * 4 + 0] + bias[c + 0];
            o.y = acc[i][jh * 4 + 1] + bias[c + 1];
            o.z = acc[i][jh * 4 + 2] + bias[c + 2];
            o.w = acc[i][jh * 4 + 3] + bias[c + 3];
            if (AVG) {
                const float4 bv = *(const float4*)&g_bb[rb * 128 + c];
                o.x += bv.x; o.y += bv.y; o.z += bv.z; o.w += bv.w;
            }
            if (res) {
                const float4 rv = *(const float4*)&res[(size_t)r * 128 + c];
                o.x += rv.x; o.y += rv.y; o.z += rv.z; o.w += rv.w;
            }
            *(float4*)&out[(size_t)r * 128 + c] = o;
        }
    }
}

// ================= avg-block: masked sums + stats ============
#define AVG_RPB 50
__global__ void avg_kernel(const float* __restrict__ x,
                           const float* __restrict__ mask) {
    const int blocksPerBatch = Nv / AVG_RPB;   // 240
    int b = blockIdx.x / blocksPerBatch;
    int n0 = (blockIdx.x % blocksPerBatch) * AVG_RPB;
    int c = threadIdx.x;                       // 128
    float s = 0.f, ms = 0.f, s1 = 0.f, q1 = 0.f;
    for (int i = 0; i < AVG_RPB; i++) {
        int row = b * Nv + n0 + i;
        float mk = mask[row];
        float xe = elu_f(x[(size_t)row * 128 + c]);
        s  += mk * xe;
        s1 += xe;
        q1 += xe * xe;
        if (c == 0) ms += mk;
    }
    atomicAdd(&g_avgsum[b * 128 + c], (double)s);
    atomicAdd(&g_sum[c], (double)s1);
    atomicAdd(&g_sumsq[c], (double)q1);
    if (c == 0) atomicAdd(&g_masksum[b], (double)ms);
}

// ================= final conv =================
__global__ void fstats_kernel(const float* __restrict__ x, int rowsPerBlock) {
    int c = threadIdx.x;                       // 128
    int r0 = blockIdx.x * rowsPerBlock;
    float s = 0.f, sq = 0.f;
    for (int r = r0; r < r0 + rowsPerBlock; r++) {
        float xv = elu_f(x[(size_t)r * 128 + c]);
        s += xv; sq += xv * xv;
    }
    atomicAdd(&g_sum[c], (double)s);
    atomicAdd(&g_sumsq[c], (double)sq);
}

__global__ void final_kernel(const float* __restrict__ f,
                             const float* __restrict__ W2,
                             const float* __restrict__ b2,
                             float* __restrict__ out) {
    int gwarp = (blockIdx.x * blockDim.x + threadIdx.x) >> 5;
    int lane = threadIdx.x & 31;
    if (gwarp >= RF) return;
    float s = 0.f;
#pragma unroll
    for (int j = 0; j < 4; j++) {
        int k = lane + j * 32;
        float xh = elu_f(f[(size_t)gwarp * 128 + k]) * g_scale[k] + g_shift[k];
        s += xh * W2[k];
    }
#pragma unroll
    for (int off = 16; off; off >>= 1) s += __shfl_down_sync(0xffffffffu, s, off);
    if (lane == 0) out[gwarp] = s + b2[0];
}

// ================= host orchestration =================
extern "C" void kernel_launch(void* const* d_in, const int* in_sizes, int n_in,
                              void* d_out, int out_size) {
    const float* inputs   = (const float*)d_in[0];
    const float* mask     = (const float*)d_in[1];
    const int*   Di_rows  = (const int*)d_in[2];
    const int*   Di_cols  = (const int*)d_in[3];
    const float* Di_vals  = (const float*)d_in[4];
    const int*   DiA_rows = (const int*)d_in[5];
    const int*   DiA_cols = (const int*)d_in[6];
    const float* DiA_vals = (const float*)d_in[7];
    const float* W1       = (const float*)d_in[8];
    const float* b1       = (const float*)d_in[9];
    const float* rn_gamma = (const float*)d_in[10];
    const float* rn_beta  = (const float*)d_in[11];
    const float* rn_W     = (const float*)d_in[12];
    const float* rn_b     = (const float*)d_in[13];
    const float* g2       = (const float*)d_in[14];
    const float* be2      = (const float*)d_in[15];
    const float* W2       = (const float*)d_in[16];
    const float* b2       = (const float*)d_in[17];
    float* out = (float*)d_out;

    float *v, *f, *msg;
    double *sum, *sumsq, *avgsum, *masksum;
    int *cnt, *startA, *startB;
    float2 *edgeA, *edgeB;
    cudaGetSymbolAddress((void**)&v, g_v);
    cudaGetSymbolAddress((void**)&f, g_f);
    cudaGetSymbolAddress((void**)&msg, g_msg);
    cudaGetSymbolAddress((void**)&sum, g_sum);
    cudaGetSymbolAddress((void**)&sumsq, g_sumsq);
    cudaGetSymbolAddress((void**)&avgsum, g_avgsum);
    cudaGetSymbolAddress((void**)&masksum, g_masksum);
    cudaGetSymbolAddress((void**)&cnt, g_cnt);
    cudaGetSymbolAddress((void**)&startA, g_startA);
    cudaGetSymbolAddress((void**)&startB, g_startB);
    cudaGetSymbolAddress((void**)&edgeA, g_edgeA);
    cudaGetSymbolAddress((void**)&edgeB, g_edgeB);

    auto clear_stats = [&]() {
        cudaMemsetAsync(sum, 0, 256 * sizeof(double), 0);
        cudaMemsetAsync(sumsq, 0, 256 * sizeof(double), 0);
    };
    auto build_csr = [&](const int* rows, const int* cols, const float* vals,
                         int* start, float2* edges) {
        cudaMemsetAsync(cnt, 0, BINS * sizeof(int), 0);
        hist_kernel<<<NNZ / 256, 256>>>(rows);
        scan_block_kernel<<<96, 1024>>>();
        scan_top_kernel<<<1, 32>>>();
        scan_finish_kernel<<<96, 1024>>>(start);
        fill_kernel<<<NNZ / 256, 256>>>(rows, cols, vals, edges);
    };

    // CSR for both sparse operators
    build_csr(DiA_rows, DiA_cols, DiA_vals, startA, edgeA);
    build_csr(Di_rows, Di_cols, Di_vals, startB, edgeB);

    // conv1 + init f = 0
    conv1_kernel<<<(RV * C) / 256, 256>>>(inputs, W1, b1);
    cudaMemsetAsync(f, 0, (size_t)RF * C * sizeof(float), 0);

    for (int i = 0; i < 16; i++) {
        const float* W0  = rn_W + (size_t)i * 2 * 256 * 128;
        const float* Wb0 = rn_b + (size_t)i * 2 * 128;
        const float* gm0 = rn_gamma + (size_t)i * 2 * 256;
        const float* bt0 = rn_beta + (size_t)i * 2 * 256;

        if ((i & 1) == 0) {
            // ---- dir block ----
            spmm_kernel<<<RV / 4, 128>>>(startA, edgeA, f, FN * C, msg, Nv * C);
            clear_stats();
            stats2_kernel<<<RV / EC_ROWS, 128>>>(v, msg);
            prep_kernel<<<1, 256>>>(gm0, bt0, 256, 1.0 / RV);
            gemm_kernel<256, false><<<RV / 128, 256>>>(v, msg, W0, Wb0, v, v);

            spmm_kernel<<<RF / 4, 128>>>(startB, edgeB, v, Nv * C, msg, FN * C);
            clear_stats();
            stats2_kernel<<<RF / EC_ROWS, 128>>>(f, msg);
            prep_kernel<<<1, 256>>>(gm0 + 256, bt0 + 256, 256, 1.0 / RF);
            gemm_kernel<256, false><<<RF / 128, 256>>>(f, msg, W0 + 256 * 128,
                                                       Wb0 + 128, nullptr, f);
        } else {
            // ---- avg block ----
            clear_stats();
            cudaMemsetAsync(avgsum, 0, Bq * C * sizeof(double), 0);
            cudaMemsetAsync(masksum, 0, Bq * sizeof(double), 0);
            avg_kernel<<<Bq * (Nv / AVG_RPB), 128>>>(v, mask);
            prep_kernel<<<1, 128>>>(gm0, bt0, 128, 1.0 / RV);
            prep_bcast_kernel<<<1, 128>>>(gm0, bt0);
            bb_kernel<<<Bq, 128>>>(W0);
            gemm_kernel<128, true><<<RV / 128, 256>>>(v, nullptr, W0, Wb0,
                                                      nullptr, msg);

            clear_stats();
            cudaMemsetAsync(avgsum, 0, Bq * C * sizeof(double), 0);
            cudaMemsetAsync(masksum, 0, Bq * sizeof(double), 0);
            avg_kernel<<<Bq * (Nv / AVG_RPB), 128>>>(msg, mask);
            prep_kernel<<<1, 128>>>(gm0 + 256, bt0 + 256, 128, 1.0 / RV);
            prep_bcast_kernel<<<1, 128>>>(gm0 + 256, bt0 + 256);
            bb_kernel<<<Bq, 128>>>(W0 + 256 * 128);
            gemm_kernel<128, true><<<RV / 128, 256>>>(msg, nullptr,
                                                      W0 + 256 * 128, Wb0 + 128,
                                                      v, v);
        }
    }

    // final conv
    clear_stats();
    fstats_kernel<<<RF / 128, 128>>>(f, 128);
    prep_kernel<<<1, 128>>>(g2, be2, 128, 1.0 / RF);
    final_kernel<<<(RF + 7) / 8, 256>>>(f, W2, b2, out);
}